// round 3
// baseline (speedup 1.0000x reference)
#include <cuda_runtime.h>
#include <cuda_bf16.h>
#include <math.h>

// Problem constants (from reference): B=8, N=256, MAX_DIM=2, D=4, EPS=1e-8
#define NP 256
#define NCELL 16   // B * MAX_DIM

// Warp-register bitonic sort of 256 floats: 8 elements per lane,
// element index e = (lane<<3) | r. Strides >=8 are cross-lane (shfl_xor),
// strides <8 are in-register.
__device__ __forceinline__ void warp_bitonic_256(float v[8], int lane) {
    #pragma unroll
    for (int k = 2; k <= 256; k <<= 1) {
        #pragma unroll
        for (int j = k >> 1; j > 0; j >>= 1) {
            if (j >= 8) {
                const int lmask = j >> 3;
                const bool upper = (lane & lmask) != 0;
                #pragma unroll
                for (int r = 0; r < 8; r++) {
                    int e = (lane << 3) | r;
                    bool asc = ((e & k) == 0);
                    float other = __shfl_xor_sync(0xffffffffu, v[r], lmask);
                    bool takeMax = (upper == asc);
                    v[r] = takeMax ? fmaxf(v[r], other) : fminf(v[r], other);
                }
            } else {
                #pragma unroll
                for (int r = 0; r < 8; r++) {
                    int ixj = r ^ j;
                    if (ixj > r) {
                        int e = (lane << 3) | r;
                        bool asc = ((e & k) == 0);
                        float lo = v[r], hi = v[ixj];
                        if ((lo > hi) == asc) { v[r] = hi; v[ixj] = lo; }
                    }
                }
            }
        }
    }
}

// Single block, 512 threads = 16 warps. Warp w handles cell w = (batch, dim):
// loads+projects set1 and set2 rows, sorts both in registers, L1-diffs the
// sorted sequences (sorted matching == optimal 1D L1 assignment), and the
// block reduces 16 partials into out[0]. One kernel launch, one barrier.
__global__ __launch_bounds__(512)
void hungarian_fused_kernel(const float* __restrict__ set1,
                            const float* __restrict__ set2,
                            float* __restrict__ out) {
    __shared__ float partial[NCELL];

    const int tid  = threadIdx.x;
    const int w    = tid >> 5;            // warp = cell 0..15
    const int lane = tid & 31;
    const int b    = w >> 1;
    const int dim  = w & 1;
    const float fdim = (float)dim;

    float va[8], vb[8];
    const float4* s1 = (const float4*)set1 + (size_t)b * NP;
    const float4* s2 = (const float4*)set2 + (size_t)b * NP;

    #pragma unroll
    for (int r = 0; r < 8; r++) {
        int e = (lane << 3) | r;
        float4 p = s1[e];
        bool m = (p.z == fdim);
        float xm = m ? p.x : 0.0f;
        float ym = m ? p.y : 0.0f;
        va[r] = xm + sqrtf(ym + 1e-8f) * 0.5f;

        float4 q = s2[e];
        // jnp.argmax over (c2, c3): first max wins -> label 1 iff c3 > c2
        bool m2 = (((q.w > q.z) ? 1 : 0) == dim);
        float xq = m2 ? q.x : 0.0f;
        float yq = m2 ? q.y : 0.0f;
        vb[r] = xq + sqrtf(yq + 1e-8f) * 0.5f;
    }

    warp_bitonic_256(va, lane);
    warp_bitonic_256(vb, lane);

    float s = 0.0f;
    #pragma unroll
    for (int r = 0; r < 8; r++) s += fabsf(va[r] - vb[r]);
    #pragma unroll
    for (int off = 16; off > 0; off >>= 1)
        s += __shfl_xor_sync(0xffffffffu, s, off);

    if (lane == 0) {
        // the 2B LAPs come in transpose pairs with equal totals -> factor 2;
        // each LAP total is averaged over N
        partial[w] = s * (2.0f / (float)NP);
    }
    __syncthreads();

    if (w == 0) {
        float t = (lane < NCELL) ? partial[lane] : 0.0f;
        #pragma unroll
        for (int off = 8; off > 0; off >>= 1)
            t += __shfl_xor_sync(0xffffffffu, t, off);
        if (lane == 0) out[0] = t;
    }
}

extern "C" void kernel_launch(void* const* d_in, const int* in_sizes, int n_in,
                              void* d_out, int out_size) {
    const float* set1 = (const float*)d_in[0];
    const float* set2 = (const float*)d_in[1];
    float* out = (float*)d_out;

    hungarian_fused_kernel<<<1, 512>>>(set1, set2, out);
}

// round 4
// speedup vs baseline: 1.2179x; 1.2179x over previous
#include <cuda_runtime.h>
#include <cuda_bf16.h>
#include <math.h>

// Problem constants (from reference): B=8, N=256, MAX_DIM=2, D=4, EPS=1e-8
#define NP 256
#define NCELL 16   // B * MAX_DIM

__device__ float g_partial[NCELL];
__device__ unsigned int g_count;   // static-init 0; atomicInc wraps back to 0

// Warp-register bitonic sort of TWO independent 256-float sequences at once
// (2-way ILP to hide SHFL latency). 8 elements per lane, e = (lane<<3)|r.
// Cross-lane strides (j>=8) use shfl_xor + min/max; in-register strides use
// branch-free fmin/fmax compare-exchange (FMNMX, lat 4 — no predicate chains).
__device__ __forceinline__ void warp_bitonic_256x2(float a[8], float b[8], int lane) {
    #pragma unroll
    for (int k = 2; k <= 256; k <<= 1) {
        #pragma unroll
        for (int j = k >> 1; j > 0; j >>= 1) {
            if (j >= 8) {
                const int lmask = j >> 3;
                const bool upper = (lane & lmask) != 0;
                #pragma unroll
                for (int r = 0; r < 8; r++) {
                    // k >= 16 here, so asc depends only on lane bits
                    bool asc = ((((lane << 3) | r) & k) == 0);
                    bool takeMax = (upper == asc);
                    float oa = __shfl_xor_sync(0xffffffffu, a[r], lmask);
                    float ob = __shfl_xor_sync(0xffffffffu, b[r], lmask);
                    a[r] = takeMax ? fmaxf(a[r], oa) : fminf(a[r], oa);
                    b[r] = takeMax ? fmaxf(b[r], ob) : fminf(b[r], ob);
                }
            } else {
                #pragma unroll
                for (int r = 0; r < 8; r++) {
                    int ixj = r ^ j;
                    if (ixj > r) {
                        bool asc = ((((lane << 3) | r) & k) == 0);
                        float alo = fminf(a[r], a[ixj]);
                        float ahi = fmaxf(a[r], a[ixj]);
                        a[r]   = asc ? alo : ahi;
                        a[ixj] = asc ? ahi : alo;
                        float blo = fminf(b[r], b[ixj]);
                        float bhi = fmaxf(b[r], b[ixj]);
                        b[r]   = asc ? blo : bhi;
                        b[ixj] = asc ? bhi : blo;
                    }
                }
            }
        }
    }
}

// 16 blocks x 32 threads: one warp per (batch, dim) cell, spread across SMs.
// Sorted matching == optimal assignment for 1D L1 cost; the 2B LAPs come in
// transpose pairs with equal totals -> factor 2. Last finishing block sums the
// 16 partials in fixed index order (deterministic) and writes out[0].
__global__ __launch_bounds__(32)
void hungarian_cells_kernel(const float* __restrict__ set1,
                            const float* __restrict__ set2,
                            float* __restrict__ out) {
    const int cell = blockIdx.x;      // 0..15
    const int b    = cell >> 1;
    const int dim  = cell & 1;
    const float fdim = (float)dim;
    const int lane = threadIdx.x;     // 0..31

    float va[8], vb[8];
    const float4* s1 = (const float4*)set1 + (size_t)b * NP;
    const float4* s2 = (const float4*)set2 + (size_t)b * NP;

    #pragma unroll
    for (int r = 0; r < 8; r++) {
        int e = (lane << 3) | r;
        float4 p = s1[e];
        bool m = (p.z == fdim);
        va[r] = (m ? p.x : 0.0f) + sqrtf((m ? p.y : 0.0f) + 1e-8f) * 0.5f;

        float4 q = s2[e];
        // jnp.argmax over (c2, c3): first max wins -> label 1 iff c3 > c2
        bool m2 = (((q.w > q.z) ? 1 : 0) == dim);
        vb[r] = (m2 ? q.x : 0.0f) + sqrtf((m2 ? q.y : 0.0f) + 1e-8f) * 0.5f;
    }

    warp_bitonic_256x2(va, vb, lane);

    float s = 0.0f;
    #pragma unroll
    for (int r = 0; r < 8; r++) s += fabsf(va[r] - vb[r]);
    #pragma unroll
    for (int off = 16; off > 0; off >>= 1)
        s += __shfl_xor_sync(0xffffffffu, s, off);

    unsigned int old = 0;
    if (lane == 0) {
        g_partial[cell] = s * (2.0f / (float)NP);
        __threadfence();
        old = atomicInc(&g_count, NCELL - 1);  // wraps 15 -> 0 (self-reset)
    }
    old = __shfl_sync(0xffffffffu, old, 0);

    if (old == NCELL - 1) {          // last block: fences ordered all partials
        float t = (lane < NCELL) ? __ldcg(&g_partial[lane]) : 0.0f;
        #pragma unroll
        for (int off = 8; off > 0; off >>= 1)
            t += __shfl_xor_sync(0xffffffffu, t, off);
        if (lane == 0) out[0] = t;
    }
}

extern "C" void kernel_launch(void* const* d_in, const int* in_sizes, int n_in,
                              void* d_out, int out_size) {
    const float* set1 = (const float*)d_in[0];
    const float* set2 = (const float*)d_in[1];
    float* out = (float*)d_out;

    hungarian_cells_kernel<<<NCELL, 32>>>(set1, set2, out);
}

// round 5
// speedup vs baseline: 1.5055x; 1.2362x over previous
#include <cuda_runtime.h>
#include <cuda_bf16.h>
#include <math.h>

// Problem constants (from reference): B=8, N=256, MAX_DIM=2, D=4, EPS=1e-8
#define NP 256
#define NCELL 16   // B * MAX_DIM

__device__ float g_partial[NCELL];
__device__ unsigned int g_count;   // static-init 0; atomicInc wraps back to 0

// 16 blocks x 512 threads. Block = one (batch, dim) cell. Threads 0..255 sort
// the set1 projection, threads 256..511 sort the set2 projection, 1 element
// per thread. Bitonic strides j>=32 exchange via smem (6 stages, 12 barriers);
// strides j<32 use shfl_xor (no barriers, latency hidden by 16 warps/block).
// Sorted matching == optimal assignment for 1D L1 cost; the 2B LAPs come in
// transpose pairs with equal totals -> factor 2. Last finishing block sums the
// 16 per-cell partials in fixed index order (deterministic) into out[0].
__global__ __launch_bounds__(512)
void hungarian_cells_kernel(const float* __restrict__ set1,
                            const float* __restrict__ set2,
                            float* __restrict__ out) {
    __shared__ float s[512];
    __shared__ float wsum[16];

    const int cell = blockIdx.x;      // 0..15
    const int b    = cell >> 1;
    const int dim  = cell & 1;
    const float fdim = (float)dim;

    const int tid  = threadIdx.x;     // 0..511
    const int n    = tid & (NP - 1);  // element index within array
    const int lane = tid & 31;
    const bool isB = (tid >= NP);

    // --- projection ---
    float v;
    if (!isB) {
        const float4 p = ((const float4*)set1)[(size_t)b * NP + n];
        bool m = (p.z == fdim);
        v = (m ? p.x : 0.0f) + sqrtf((m ? p.y : 0.0f) + 1e-8f) * 0.5f;
    } else {
        const float4 q = ((const float4*)set2)[(size_t)b * NP + n];
        // jnp.argmax over (c2, c3): first max wins -> label 1 iff c3 > c2
        bool m2 = (((q.w > q.z) ? 1 : 0) == dim);
        v = (m2 ? q.x : 0.0f) + sqrtf((m2 ? q.y : 0.0f) + 1e-8f) * 0.5f;
    }

    // --- bitonic sort, 1 elem/thread, both arrays concurrently ---
    #pragma unroll
    for (int k = 2; k <= NP; k <<= 1) {
        #pragma unroll
        for (int j = k >> 1; j > 0; j >>= 1) {
            const bool asc     = ((n & k) == 0);
            const bool upper   = ((n & j) != 0);
            const bool takeMax = (upper == asc);
            float o;
            if (j >= 32) {
                __syncthreads();          // previous stage's reads complete
                s[tid] = v;
                __syncthreads();
                o = s[tid ^ j];           // partner stays within same array half
            } else {
                o = __shfl_xor_sync(0xffffffffu, v, j);
            }
            v = takeMax ? fmaxf(v, o) : fminf(v, o);
        }
    }

    // --- L1 diff of sorted sequences + block reduce ---
    __syncthreads();
    s[tid] = v;
    __syncthreads();
    float d = isB ? 0.0f : fabsf(s[n] - s[n + NP]);
    #pragma unroll
    for (int off = 16; off > 0; off >>= 1)
        d += __shfl_xor_sync(0xffffffffu, d, off);
    if (lane == 0) wsum[tid >> 5] = d;    // warps 8..15 write 0
    __syncthreads();

    if (tid < 32) {
        float t = (lane < 16) ? wsum[lane] : 0.0f;
        #pragma unroll
        for (int off = 8; off > 0; off >>= 1)
            t += __shfl_xor_sync(0xffffffffu, t, off);
        if (lane == 0) {
            // transpose-pair symmetry -> factor 2; each LAP averaged over N
            g_partial[cell] = t * (2.0f / (float)NP);
            __threadfence();
            unsigned int old = atomicInc(&g_count, NCELL - 1);  // 15 -> wraps 0
            if (old == NCELL - 1) {       // last block: all partials visible
                float tot = 0.0f;
                #pragma unroll
                for (int i = 0; i < NCELL; i++) tot += __ldcg(&g_partial[i]);
                out[0] = tot;
            }
        }
    }
}

extern "C" void kernel_launch(void* const* d_in, const int* in_sizes, int n_in,
                              void* d_out, int out_size) {
    const float* set1 = (const float*)d_in[0];
    const float* set2 = (const float*)d_in[1];
    float* out = (float*)d_out;

    hungarian_cells_kernel<<<NCELL, 512>>>(set1, set2, out);
}

// round 6
// speedup vs baseline: 1.8716x; 1.2431x over previous
#include <cuda_runtime.h>
#include <cuda_bf16.h>
#include <math.h>

// Problem constants (from reference): B=8, N=256, MAX_DIM=2, D=4, EPS=1e-8
#define NP 256
#define NCELL 16   // B * MAX_DIM

__device__ float g_partial[NCELL];
__device__ unsigned int g_count;   // static-init 0; atomicInc wraps back to 0

// 16 blocks x 256 threads. Block = one (batch, dim) cell. Threads 0..127 sort
// the set1 projection, threads 128..255 sort set2, TWO elements per thread
// (e = 2t, 2t+1). Stage dispatch by stride j:
//   j == 1      : in-register compare-exchange           (8 stages)
//   2 <= j <= 32: shfl_xor within warp, no barriers      (25 stages)
//   j >= 64     : double-buffered smem, ONE barrier each (3 stages)
// Sorted matching == optimal assignment for 1D L1 cost; the 2B LAPs come in
// transpose pairs with equal totals -> factor 2. Last finishing block sums the
// 16 per-cell partials in fixed index order (deterministic) into out[0].
__global__ __launch_bounds__(256)
void hungarian_cells_kernel(const float* __restrict__ set1,
                            const float* __restrict__ set2,
                            float* __restrict__ out) {
    __shared__ float buf0[512];
    __shared__ float buf1[512];
    __shared__ float wsum[4];

    const int cell = blockIdx.x;      // 0..15
    const int b    = cell >> 1;
    const int dim  = cell & 1;
    const float fdim = (float)dim;

    const int tid  = threadIdx.x;     // 0..255
    const int half = tid >> 7;        // 0 = set1 array, 1 = set2 array
    const int t    = tid & 127;       // thread index within array
    const int lane = tid & 31;

    // --- projection: elements e = 2t, 2t+1 ---
    float v0, v1;
    if (half == 0) {
        const float4* s1 = (const float4*)set1 + (size_t)b * NP + 2 * t;
        float4 p = s1[0];
        bool m = (p.z == fdim);
        v0 = (m ? p.x : 0.0f) + sqrtf((m ? p.y : 0.0f) + 1e-8f) * 0.5f;
        p = s1[1];
        m = (p.z == fdim);
        v1 = (m ? p.x : 0.0f) + sqrtf((m ? p.y : 0.0f) + 1e-8f) * 0.5f;
    } else {
        const float4* s2 = (const float4*)set2 + (size_t)b * NP + 2 * t;
        float4 q = s2[0];
        // jnp.argmax over (c2, c3): first max wins -> label 1 iff c3 > c2
        bool m = (((q.w > q.z) ? 1 : 0) == dim);
        v0 = (m ? q.x : 0.0f) + sqrtf((m ? q.y : 0.0f) + 1e-8f) * 0.5f;
        q = s2[1];
        m = (((q.w > q.z) ? 1 : 0) == dim);
        v1 = (m ? q.x : 0.0f) + sqrtf((m ? q.y : 0.0f) + 1e-8f) * 0.5f;
    }

    // --- bitonic sort of 256 elements, 2 per thread ---
    int phase = 0;
    #pragma unroll
    for (int k = 2; k <= NP; k <<= 1) {
        #pragma unroll
        for (int j = k >> 1; j > 0; j >>= 1) {
            const bool asc = (((2 * t) & k) == 0);   // same for both elems
            if (j == 1) {
                float lo = fminf(v0, v1);
                float hi = fmaxf(v0, v1);
                v0 = asc ? lo : hi;
                v1 = asc ? hi : lo;
            } else if (j <= 32) {
                const int lm = j >> 1;                // partner lane mask
                const bool takeMax = (((t & lm) != 0) == asc);
                float o0 = __shfl_xor_sync(0xffffffffu, v0, lm);
                float o1 = __shfl_xor_sync(0xffffffffu, v1, lm);
                v0 = takeMax ? fmaxf(v0, o0) : fminf(v0, o0);
                v1 = takeMax ? fmaxf(v1, o1) : fminf(v1, o1);
            } else {                                  // j = 64 or 128: smem
                float* w = phase ? buf1 : buf0;
                phase ^= 1;
                const int base = half * 256 + 2 * t;
                ((float2*)(w + base))[0] = make_float2(v0, v1);
                __syncthreads();
                const int pb = half * 256 + ((2 * t) ^ j);
                float2 o = ((float2*)(w + pb))[0];
                const bool takeMax = (((t & (j >> 1)) != 0) == asc);
                v0 = takeMax ? fmaxf(v0, o.x) : fminf(v0, o.x);
                v1 = takeMax ? fmaxf(v1, o.y) : fminf(v1, o.y);
            }
        }
    }

    // --- L1 diff of sorted sequences ---
    {
        float* w = phase ? buf1 : buf0;
        if (half == 1) ((float2*)(w + 256 + 2 * t))[0] = make_float2(v0, v1);
        __syncthreads();
        float d = 0.0f;
        if (half == 0) {
            float2 o = ((float2*)(w + 256 + 2 * t))[0];
            d = fabsf(v0 - o.x) + fabsf(v1 - o.y);
        }
        #pragma unroll
        for (int off = 16; off > 0; off >>= 1)
            d += __shfl_xor_sync(0xffffffffu, d, off);
        if (half == 0 && lane == 0) wsum[t >> 5] = d;   // warps 0..3
    }
    __syncthreads();

    if (tid < 32) {
        float s = (lane < 4) ? wsum[lane] : 0.0f;
        s += __shfl_xor_sync(0xffffffffu, s, 2);
        s += __shfl_xor_sync(0xffffffffu, s, 1);
        if (lane == 0) {
            // transpose-pair symmetry -> factor 2; each LAP averaged over N
            g_partial[cell] = s * (2.0f / (float)NP);
            __threadfence();
            unsigned int old = atomicInc(&g_count, NCELL - 1);  // 15 -> wraps 0
            if (old == NCELL - 1) {       // last block: all partials visible
                float tot = 0.0f;
                #pragma unroll
                for (int i = 0; i < NCELL; i++) tot += __ldcg(&g_partial[i]);
                out[0] = tot;
            }
        }
    }
}

extern "C" void kernel_launch(void* const* d_in, const int* in_sizes, int n_in,
                              void* d_out, int out_size) {
    const float* set1 = (const float*)d_in[0];
    const float* set2 = (const float*)d_in[1];
    float* out = (float*)d_out;

    hungarian_cells_kernel<<<NCELL, 256>>>(set1, set2, out);
}